// round 8
// baseline (speedup 1.0000x reference)
#include <cuda_runtime.h>
#include <cuda_fp16.h>
#include <math.h>
#include <stdint.h>

#define N_POI 50000
#define DIM 128
#define E_EDGES 400000
#define GCN_NUM 3
#define BATCH 64
#define LSEQ 100
#define NTOK (BATCH*LSEQ)
#define DIRE (2*E_EDGES)

// ---------------- device scratch (static, no allocations) ----------------
__device__ __align__(16) int    g_cnt[N_POI];
__device__ __align__(16) int    g_rowptr[N_POI+1];
__device__ __align__(16) int    g_rowcur[N_POI];
__device__ __align__(16) float  g_dis[N_POI];
__device__ __align__(16) int    g_colidx[DIRE];
__device__ __align__(16) float  g_wcsr[DIRE];
__device__ __align__(16) float  g_bufA[N_POI*DIM];
__device__ __align__(16) float  g_agg[N_POI*DIM];
__device__ __align__(16) __half g_encH[N_POI*DIM];   // fp16 mirror for SpMM gather
__device__ __align__(16) float  g_qkv[NTOK*3*DIM];
__device__ __align__(16) float  g_o[NTOK*DIM];

// tf32 helpers
__device__ __forceinline__ uint32_t to_tf32(float x){
    uint32_t u;
    asm("cvt.rna.tf32.f32 %0, %1;" : "=r"(u) : "f"(x));
    return u;
}
__device__ __forceinline__ void mma_tf32(float* d, const uint32_t* a, const uint32_t* b){
    asm volatile("mma.sync.aligned.m16n8k8.row.col.f32.tf32.tf32.f32 "
        "{%0,%1,%2,%3}, {%4,%5,%6,%7}, {%8,%9}, {%0,%1,%2,%3};"
        : "+f"(d[0]), "+f"(d[1]), "+f"(d[2]), "+f"(d[3])
        : "r"(a[0]), "r"(a[1]), "r"(a[2]), "r"(a[3]), "r"(b[0]), "r"(b[1]));
}

// ---------------- hist + fp16 convert fused (kernel launch #1) ----------------
__global__ void k_hist_cvt(const int* __restrict__ e0, const int* __restrict__ e1,
                           int* cnt, const float4* __restrict__ x4,
                           __half2* __restrict__ yh2){
    int i = blockIdx.x*256 + threadIdx.x;
    if (i < E_EDGES){
        atomicAdd(&cnt[e0[i]], 1);
        atomicAdd(&cnt[e1[i]], 1);
    }
    for (int j = i; j < N_POI*32; j += gridDim.x*256){
        float4 v = x4[j];
        yh2[j*2]     = __floats2half2_rn(v.x, v.y);
        yh2[j*2 + 1] = __floats2half2_rn(v.z, v.w);
    }
}
// ---------------- scan (#2) ----------------
__global__ void k_scan(const int* __restrict__ cnt, int* __restrict__ rowptr,
                       int* __restrict__ rowcur, float* __restrict__ dis){
    __shared__ int sh[1024];
    int t = threadIdx.x;
    const int CH = (N_POI + 1023)/1024;
    int base = t*CH;
    int s = 0;
    for (int i = 0; i < CH; i++){
        int idx = base + i;
        if (idx < N_POI) s += cnt[idx];
    }
    sh[t] = s;
    __syncthreads();
    for (int o = 1; o < 1024; o <<= 1){
        int v = (t >= o) ? sh[t-o] : 0;
        __syncthreads();
        sh[t] += v;
        __syncthreads();
    }
    int off = (t == 0) ? 0 : sh[t-1];
    for (int i = 0; i < CH; i++){
        int idx = base + i;
        if (idx < N_POI){
            int c = cnt[idx];
            rowptr[idx] = off;
            rowcur[idx] = off;
            dis[idx] = rsqrtf((float)(c + 1));
            off += c;
        }
    }
    if (t == 1023) rowptr[N_POI] = sh[1023];
}
// ---------------- scatter (#3) ----------------
__global__ void k_scatter(const int* __restrict__ e0, const int* __restrict__ e1,
                          const float* __restrict__ dv, const float* __restrict__ dis,
                          int* rowcur, int* __restrict__ colidx, float* __restrict__ wcsr){
    int e = blockIdx.x*256 + threadIdx.x;
    if (e >= E_EDGES) return;
    int a = e0[e], b = e1[e];
    float d = dv[e];
    float wv = expf(-d*d) * dis[a] * dis[b];
    int p = atomicAdd(&rowcur[a], 1);
    colidx[p] = b; wcsr[p] = wv;
    p = atomicAdd(&rowcur[b], 1);
    colidx[p] = a; wcsr[p] = wv;
}

// ---------------- SpMM (#4, gets ncu capture): warp-batched indices + fp16 gather ----------------
__global__ void __launch_bounds__(256)
k_spmm3(const uint2* __restrict__ encH2, const int* __restrict__ rowptr,
        const int* __restrict__ cols, const float* __restrict__ ws,
        const float* __restrict__ dis, float4* __restrict__ agg4){
    int row = blockIdx.x*8 + (threadIdx.x >> 5);
    int lane = threadIdx.x & 31;
    if (row >= N_POI) return;
    float ds = dis[row];
    float sl = ds*ds;

    uint2 xs = __ldg(&encH2[row*32 + lane]);
    float2 xa = __half22float2(*(const __half2*)&xs.x);
    float2 xb = __half22float2(*(const __half2*)&xs.y);
    float4 acc = make_float4(sl*xa.x, sl*xa.y, sl*xb.x, sl*xb.y);

    int s = __ldg(&rowptr[row]), e = __ldg(&rowptr[row+1]);
    for (int base = s; base < e; base += 32){
        int n = e - base;
        if (n > 32) n = 32;
        int cc = 0; float ww = 0.f;
        if (lane < n){
            cc = __ldg(&cols[base + lane]);
            ww = __ldg(&ws[base + lane]);
        }
        int j = 0;
        for (; j + 4 <= n; j += 4){
            int c0 = __shfl_sync(0xffffffffu, cc, j);
            int c1 = __shfl_sync(0xffffffffu, cc, j+1);
            int c2 = __shfl_sync(0xffffffffu, cc, j+2);
            int c3 = __shfl_sync(0xffffffffu, cc, j+3);
            float w0 = __shfl_sync(0xffffffffu, ww, j);
            float w1 = __shfl_sync(0xffffffffu, ww, j+1);
            float w2 = __shfl_sync(0xffffffffu, ww, j+2);
            float w3 = __shfl_sync(0xffffffffu, ww, j+3);
            uint2 u0 = __ldg(&encH2[c0*32 + lane]);
            uint2 u1 = __ldg(&encH2[c1*32 + lane]);
            uint2 u2 = __ldg(&encH2[c2*32 + lane]);
            uint2 u3 = __ldg(&encH2[c3*32 + lane]);
            float2 a0 = __half22float2(*(const __half2*)&u0.x), b0 = __half22float2(*(const __half2*)&u0.y);
            float2 a1 = __half22float2(*(const __half2*)&u1.x), b1 = __half22float2(*(const __half2*)&u1.y);
            float2 a2 = __half22float2(*(const __half2*)&u2.x), b2 = __half22float2(*(const __half2*)&u2.y);
            float2 a3 = __half22float2(*(const __half2*)&u3.x), b3 = __half22float2(*(const __half2*)&u3.y);
            acc.x = fmaf(w3,a3.x, fmaf(w2,a2.x, fmaf(w1,a1.x, fmaf(w0,a0.x, acc.x))));
            acc.y = fmaf(w3,a3.y, fmaf(w2,a2.y, fmaf(w1,a1.y, fmaf(w0,a0.y, acc.y))));
            acc.z = fmaf(w3,b3.x, fmaf(w2,b2.x, fmaf(w1,b1.x, fmaf(w0,b0.x, acc.z))));
            acc.w = fmaf(w3,b3.y, fmaf(w2,b2.y, fmaf(w1,b1.y, fmaf(w0,b0.y, acc.w))));
        }
        for (; j < n; j++){
            int c = __shfl_sync(0xffffffffu, cc, j);
            float w = __shfl_sync(0xffffffffu, ww, j);
            uint2 u = __ldg(&encH2[c*32 + lane]);
            float2 a = __half22float2(*(const __half2*)&u.x);
            float2 b = __half22float2(*(const __half2*)&u.y);
            acc.x = fmaf(w, a.x, acc.x);
            acc.y = fmaf(w, a.y, acc.y);
            acc.z = fmaf(w, b.x, acc.z);
            acc.w = fmaf(w, b.y, acc.w);
        }
    }
    agg4[row*32 + lane] = acc;
}

// ================= tf32 mma.sync GEMM + lrelu + row L2-norm =================
#define GP 132
__global__ void __launch_bounds__(256, 1)
k_gemm_tf32(const float4* __restrict__ X4, const float* __restrict__ W,
            const float* __restrict__ bias, float* __restrict__ Y,
            __half2* __restrict__ Yh2, int M){
    extern __shared__ uint32_t sh[];
    uint32_t* As = sh;
    uint32_t* Bs = sh + 128*GP;
    __shared__ float ssred[128][4];
    __shared__ float sscale[128];
    int tid = threadIdx.x;
    int row0 = blockIdx.x * 128;

    const float4* W4 = (const float4*)W;
    for (int i = tid; i < 128*32; i += 256){
        int r = i >> 5, c4 = i & 31;
        int grow = row0 + r;
        float4 v = (grow < M) ? X4[grow*32 + c4] : make_float4(0.f,0.f,0.f,0.f);
        float4 wv = W4[i];
        int base = r*GP + c4*4;
        uint4 av = make_uint4(to_tf32(v.x),  to_tf32(v.y),  to_tf32(v.z),  to_tf32(v.w));
        uint4 bv = make_uint4(to_tf32(wv.x), to_tf32(wv.y), to_tf32(wv.z), to_tf32(wv.w));
        *(uint4*)&As[base] = av;
        *(uint4*)&Bs[base] = bv;
    }
    __syncthreads();

    int wid = tid >> 5, lane = tid & 31;
    int wm = wid & 1, wn = wid >> 1;
    int m_base = wm*64, n_base = wn*32;
    int qr = lane >> 2, qc = lane & 3;

    float acc[4][4][4];
    #pragma unroll
    for (int mi = 0; mi < 4; mi++)
        #pragma unroll
        for (int ni = 0; ni < 4; ni++)
            #pragma unroll
            for (int j = 0; j < 4; j++) acc[mi][ni][j] = 0.f;

    #pragma unroll 2
    for (int k0 = 0; k0 < 128; k0 += 8){
        uint32_t a[4][4];
        #pragma unroll
        for (int mi = 0; mi < 4; mi++){
            const uint32_t* ap = As + (m_base + mi*16 + qr)*GP + k0 + qc;
            a[mi][0] = ap[0];
            a[mi][1] = ap[8*GP];
            a[mi][2] = ap[4];
            a[mi][3] = ap[8*GP + 4];
        }
        uint32_t b[4][2];
        #pragma unroll
        for (int ni = 0; ni < 4; ni++){
            const uint32_t* bp = Bs + (n_base + ni*8 + qr)*GP + k0 + qc;
            b[ni][0] = bp[0];
            b[ni][1] = bp[4];
        }
        #pragma unroll
        for (int mi = 0; mi < 4; mi++)
            #pragma unroll
            for (int ni = 0; ni < 4; ni++)
                mma_tf32(acc[mi][ni], a[mi], b[ni]);
    }

    float2 bv[4];
    #pragma unroll
    for (int ni = 0; ni < 4; ni++)
        bv[ni] = *(const float2*)&bias[n_base + ni*8 + qc*2];

    float ss[4][2];
    #pragma unroll
    for (int mi = 0; mi < 4; mi++){ ss[mi][0] = 0.f; ss[mi][1] = 0.f; }
    #pragma unroll
    for (int mi = 0; mi < 4; mi++)
        #pragma unroll
        for (int ni = 0; ni < 4; ni++){
            float* d = acc[mi][ni];
            float t0 = d[0] + bv[ni].x, t1 = d[1] + bv[ni].y;
            float t2 = d[2] + bv[ni].x, t3 = d[3] + bv[ni].y;
            t0 = (t0 >= 0.f) ? t0 : 0.01f*t0;
            t1 = (t1 >= 0.f) ? t1 : 0.01f*t1;
            t2 = (t2 >= 0.f) ? t2 : 0.01f*t2;
            t3 = (t3 >= 0.f) ? t3 : 0.01f*t3;
            d[0] = t0; d[1] = t1; d[2] = t2; d[3] = t3;
            ss[mi][0] = fmaf(t0,t0, fmaf(t1,t1, ss[mi][0]));
            ss[mi][1] = fmaf(t2,t2, fmaf(t3,t3, ss[mi][1]));
        }
    #pragma unroll
    for (int mi = 0; mi < 4; mi++)
        #pragma unroll
        for (int hf = 0; hf < 2; hf++){
            float v = ss[mi][hf];
            v += __shfl_xor_sync(0xffffffffu, v, 1);
            v += __shfl_xor_sync(0xffffffffu, v, 2);
            if (qc == 0) ssred[m_base + mi*16 + qr + hf*8][wn] = v;
        }
    __syncthreads();
    if (tid < 128){
        float t = ssred[tid][0] + ssred[tid][1] + ssred[tid][2] + ssred[tid][3];
        sscale[tid] = 1.0f / fmaxf(sqrtf(t), 1e-12f);
    }
    __syncthreads();

    #pragma unroll
    for (int mi = 0; mi < 4; mi++){
        int lr0 = m_base + mi*16 + qr;
        int lr1 = lr0 + 8;
        float s0 = sscale[lr0], s1 = sscale[lr1];
        int r0 = row0 + lr0, r1 = row0 + lr1;
        #pragma unroll
        for (int ni = 0; ni < 4; ni++){
            float* d = acc[mi][ni];
            int col = n_base + ni*8 + qc*2;
            if (r0 < M){
                float y0 = d[0]*s0, y1 = d[1]*s0;
                *(float2*)&Y[r0*DIM + col] = make_float2(y0, y1);
                Yh2[r0*64 + (col >> 1)] = __floats2half2_rn(y0, y1);
            }
            if (r1 < M){
                float y2 = d[2]*s1, y3 = d[3]*s1;
                *(float2*)&Y[r1*DIM + col] = make_float2(y2, y3);
                Yh2[r1*64 + (col >> 1)] = __floats2half2_rn(y2, y3);
            }
        }
    }
}

// ---------------- QKV: scalar tiled GEMM ----------------
__global__ void __launch_bounds__(256, 1)
k_qkv2(const float4* __restrict__ enc4, const int* __restrict__ xidx,
       const float* __restrict__ inw, const float* __restrict__ inb,
       float4* __restrict__ qkv4){
    extern __shared__ float4 sh4[];
    float4* Xs = sh4;
    float4* Ws = sh4 + 4096;
    int tid = threadIdx.x;
    int row0 = blockIdx.x * 128;
    int nb = blockIdx.y;
    #pragma unroll
    for (int it = 0; it < 16; it++){
        int idx = tid + it*256;
        int m = idx >> 5, k4 = idx & 31;
        int src = __ldg(&xidx[row0 + m]);
        Xs[idx] = enc4[src*32 + k4];
    }
    const float4* W4 = (const float4*)(inw + nb*DIM*DIM);
    #pragma unroll
    for (int it = 0; it < 16; it++){
        int idx = tid + it*256;
        int n = idx >> 5, k4 = idx & 31;
        Ws[n*32 + (k4 ^ (n >> 3))] = W4[idx];
    }
    __syncthreads();

    int tx = tid & 15, ty = tid >> 4;
    float acc[8][8];
    #pragma unroll
    for (int r = 0; r < 8; r++)
        #pragma unroll
        for (int c = 0; c < 8; c++) acc[r][c] = 0.f;

    const float4* Xp = Xs + (ty*8)*32;
    const float4* Wp = Ws + (tx*8)*32;
    #pragma unroll 2
    for (int k4 = 0; k4 < 32; k4++){
        float4 xv[8], wv[8];
        #pragma unroll
        for (int r = 0; r < 8; r++) xv[r] = Xp[r*32 + k4];
        int ksw = k4 ^ tx;
        #pragma unroll
        for (int c = 0; c < 8; c++) wv[c] = Wp[c*32 + ksw];
        #pragma unroll
        for (int r = 0; r < 8; r++)
            #pragma unroll
            for (int c = 0; c < 8; c++){
                acc[r][c] = fmaf(xv[r].x, wv[c].x, acc[r][c]);
                acc[r][c] = fmaf(xv[r].y, wv[c].y, acc[r][c]);
                acc[r][c] = fmaf(xv[r].z, wv[c].z, acc[r][c]);
                acc[r][c] = fmaf(xv[r].w, wv[c].w, acc[r][c]);
            }
    }

    float bj[8];
    #pragma unroll
    for (int c = 0; c < 8; c++) bj[c] = __ldg(&inb[nb*DIM + tx*8 + c]);
    #pragma unroll
    for (int r = 0; r < 8; r++){
        int t = row0 + ty*8 + r;
        qkv4[t*96 + nb*32 + tx*2]     = make_float4(acc[r][0]+bj[0], acc[r][1]+bj[1], acc[r][2]+bj[2], acc[r][3]+bj[3]);
        qkv4[t*96 + nb*32 + tx*2 + 1] = make_float4(acc[r][4]+bj[4], acc[r][5]+bj[5], acc[r][6]+bj[6], acc[r][7]+bj[7]);
    }
}

// ---------------- attention: conflict-free, one block per (b, h) ----------------
__global__ void k_attn(const float* __restrict__ qkv, float* __restrict__ o){
    extern __shared__ float sha[];
    float* sq  = sha;
    float* skT = sha + LSEQ*16;
    float* sv  = sha + 2*LSEQ*16;
    float* sp  = sha + 3*LSEQ*16;
    int b = blockIdx.x, h = blockIdx.y;
    int tid = threadIdx.x;
    for (int idx = tid; idx < LSEQ*16; idx += 128){
        int t = idx >> 4, d = idx & 15;
        int base = (b*LSEQ + t)*(3*DIM) + h*16 + d;
        sq[idx] = qkv[base];
        sv[idx] = qkv[base + 2*DIM];
    }
    for (int idx = tid; idx < LSEQ*16; idx += 128){
        int d = idx / LSEQ, t = idx - d*LSEQ;
        skT[idx] = qkv[(b*LSEQ + t)*(3*DIM) + DIM + h*16 + d];
    }
    __syncthreads();

    int lane = tid & 31, warp = tid >> 5;
    for (int qi = warp; qi < LSEQ; qi += 4){
        float q[16];
        #pragma unroll
        for (int d = 0; d < 16; d++) q[d] = sq[qi*16 + d];
        float v[4];
        float m = -1e30f;
        #pragma unroll
        for (int g = 0; g < 4; g++){
            int j = lane + g*32;
            float s = -1e30f;
            if (j < LSEQ){
                s = 0.f;
                #pragma unroll
                for (int d = 0; d < 16; d++) s = fmaf(q[d], skT[d*LSEQ + j], s);
                s *= 0.25f;
            }
            v[g] = s;
            m = fmaxf(m, s);
        }
        #pragma unroll
        for (int t = 16; t > 0; t >>= 1) m = fmaxf(m, __shfl_xor_sync(0xffffffffu, m, t));
        float ssum = 0.f;
        #pragma unroll
        for (int g = 0; g < 4; g++){
            int j = lane + g*32;
            float p = (j < LSEQ) ? __expf(v[g] - m) : 0.f;
            v[g] = p;
            ssum += p;
        }
        #pragma unroll
        for (int t = 16; t > 0; t >>= 1) ssum += __shfl_xor_sync(0xffffffffu, ssum, t);
        float inv = 1.0f / ssum;
        #pragma unroll
        for (int g = 0; g < 4; g++){
            int j = lane + g*32;
            if (j < LSEQ) sp[qi*LSEQ + j] = v[g]*inv;
        }
    }
    __syncthreads();

    const float4* sv4 = (const float4*)sv;
    for (int u = tid; u < LSEQ*4; u += 128){
        int qi = u >> 2, dg = u & 3;
        float4 acc = make_float4(0.f,0.f,0.f,0.f);
        const float* pp = sp + qi*LSEQ;
        #pragma unroll 4
        for (int j = 0; j < LSEQ; j++){
            float p = pp[j];
            float4 vv = sv4[j*4 + dg];
            acc.x = fmaf(p, vv.x, acc.x);
            acc.y = fmaf(p, vv.y, acc.y);
            acc.z = fmaf(p, vv.z, acc.z);
            acc.w = fmaf(p, vv.w, acc.w);
        }
        *(float4*)&o[(b*LSEQ + qi)*DIM + h*16 + dg*4] = acc;
    }
}

// ---------------- mean over L + out-projection + target gather ----------------
__global__ void k_tail(const float* __restrict__ o, const float* __restrict__ ow,
                       const float* __restrict__ ob, const float* __restrict__ enc,
                       const int* __restrict__ pidx, float* __restrict__ out){
    __shared__ float sx[DIM];
    int b = blockIdx.x, j = threadIdx.x;
    float s = 0.0f;
    for (int i = 0; i < LSEQ; i++) s += o[(b*LSEQ + i)*DIM + j];
    sx[j] = s * (1.0f/LSEQ);
    __syncthreads();
    float acc = ob[j];
    #pragma unroll 4
    for (int k = 0; k < DIM; k++) acc += sx[k]*ow[j*DIM + k];
    out[b*DIM + j] = acc;
    out[BATCH*DIM + b*DIM + j] = enc[pidx[b]*DIM + j];
}

// ---------------- host launch ----------------
extern "C" void kernel_launch(void* const* d_in, const int* in_sizes, int n_in,
                              void* d_out, int out_size){
    const float* embeds = (const float*)d_in[0];
    const float* gcnW   = (const float*)d_in[1];
    const float* gcnb   = (const float*)d_in[2];
    const float* inw    = (const float*)d_in[3];
    const float* inb    = (const float*)d_in[4];
    const float* ow     = (const float*)d_in[5];
    const float* ob     = (const float*)d_in[6];
    const float* dv     = (const float*)d_in[7];
    const int*   edges  = (const int*)d_in[8];
    const int*   xidx   = (const int*)d_in[9];
    const int*   pidx   = (const int*)d_in[10];
    const int* e0 = edges;
    const int* e1 = edges + E_EDGES;
    float* out = (float*)d_out;

    int *cnt, *rowptr, *rowcur, *colidx;
    float *dis, *wcsr, *agg, *bA, *qkv, *obuf;
    __half* encH;
    cudaGetSymbolAddress((void**)&cnt,    g_cnt);
    cudaGetSymbolAddress((void**)&rowptr, g_rowptr);
    cudaGetSymbolAddress((void**)&rowcur, g_rowcur);
    cudaGetSymbolAddress((void**)&dis,    g_dis);
    cudaGetSymbolAddress((void**)&colidx, g_colidx);
    cudaGetSymbolAddress((void**)&wcsr,   g_wcsr);
    cudaGetSymbolAddress((void**)&agg,    g_agg);
    cudaGetSymbolAddress((void**)&bA,     g_bufA);
    cudaGetSymbolAddress((void**)&encH,   g_encH);
    cudaGetSymbolAddress((void**)&qkv,    g_qkv);
    cudaGetSymbolAddress((void**)&obuf,   g_o);

    const int smem_qkv  = 2*4096*(int)sizeof(float4);
    const int smem_gemm = 2*128*GP*(int)sizeof(uint32_t);
    const int smem_attn = (3*LSEQ*16 + LSEQ*LSEQ)*(int)sizeof(float);
    cudaFuncSetAttribute(k_gemm_tf32, cudaFuncAttributeMaxDynamicSharedMemorySize, smem_gemm);
    cudaFuncSetAttribute(k_qkv2,      cudaFuncAttributeMaxDynamicSharedMemorySize, smem_qkv);
    cudaFuncSetAttribute(k_attn,      cudaFuncAttributeMaxDynamicSharedMemorySize, smem_attn);

    // CSR build; launch order arranged so kernel #4 (ncu capture slot) = k_spmm3
    cudaMemsetAsync(cnt, 0, N_POI*sizeof(int));
    k_hist_cvt<<<(N_POI*32+255)/256, 256>>>(e0, e1, cnt, (const float4*)embeds,
                                            (__half2*)encH);                 // #1
    k_scan<<<1, 1024>>>(cnt, rowptr, rowcur, dis);                           // #2
    k_scatter<<<(E_EDGES+255)/256, 256>>>(e0, e1, dv, dis, rowcur, colidx, wcsr); // #3

    // 3 GCN layers
    for (int i = 0; i < GCN_NUM; i++){
        k_spmm3<<<(N_POI+7)/8, 256>>>((const uint2*)encH, rowptr, colidx, wcsr, dis,
                                       (float4*)agg);                        // #4 (first iter)
        k_gemm_tf32<<<(N_POI+127)/128, 256, smem_gemm>>>(
            (const float4*)agg, gcnW + i*DIM*DIM, gcnb + i*DIM, bA, (__half2*)encH, N_POI);
    }
    const float* encF = bA;

    // attention
    k_qkv2<<<dim3(NTOK/128, 3), 256, smem_qkv>>>((const float4*)encF, xidx, inw, inb,
                                                 (float4*)qkv);
    k_attn<<<dim3(BATCH, 8), 128, smem_attn>>>(qkv, obuf);
    k_tail<<<BATCH, 128>>>(obuf, ow, ob, encF, pidx, out);
}

// round 9
// speedup vs baseline: 1.0605x; 1.0605x over previous
#include <cuda_runtime.h>
#include <cuda_fp16.h>
#include <math.h>
#include <stdint.h>

#define N_POI 50000
#define DIM 128
#define E_EDGES 400000
#define GCN_NUM 3
#define BATCH 64
#define LSEQ 100
#define NTOK (BATCH*LSEQ)
#define DIRE (2*E_EDGES)

// ---------------- device scratch ----------------
__device__ __align__(16) int    g_cnt[N_POI];
__device__ __align__(16) int    g_rowptr[N_POI+1];
__device__ __align__(16) int    g_rowcur[N_POI];
__device__ __align__(16) float  g_dis[N_POI];
__device__ __align__(16) int    g_colidx[DIRE];
__device__ __align__(16) float  g_wcsr[DIRE];
__device__ __align__(16) float  g_bufA[N_POI*DIM];
__device__ __align__(16) float  g_agg[N_POI*DIM];
__device__ __align__(16) __half g_encH[N_POI*DIM];
__device__ __align__(16) float  g_qkv[NTOK*3*DIM];
__device__ __align__(16) float  g_o[NTOK*DIM];

// tf32 helpers
__device__ __forceinline__ uint32_t to_tf32(float x){
    uint32_t u;
    asm("cvt.rna.tf32.f32 %0, %1;" : "=r"(u) : "f"(x));
    return u;
}
__device__ __forceinline__ void mma_tf32(float* d, const uint32_t* a, const uint32_t* b){
    asm volatile("mma.sync.aligned.m16n8k8.row.col.f32.tf32.tf32.f32 "
        "{%0,%1,%2,%3}, {%4,%5,%6,%7}, {%8,%9}, {%0,%1,%2,%3};"
        : "+f"(d[0]), "+f"(d[1]), "+f"(d[2]), "+f"(d[3])
        : "r"(a[0]), "r"(a[1]), "r"(a[2]), "r"(a[3]), "r"(b[0]), "r"(b[1]));
}

// ---------------- #1: embeds -> fp16 mirror ----------------
__global__ void k_cvt_h(const float4* __restrict__ x4, __half2* __restrict__ yh2, int n4){
    int i = blockIdx.x*256 + threadIdx.x;
    if (i < n4){
        float4 v = x4[i];
        yh2[i*2]     = __floats2half2_rn(v.x, v.y);
        yh2[i*2 + 1] = __floats2half2_rn(v.z, v.w);
    }
}
// ---------------- #2: histogram ----------------
__global__ void k_hist(const int* __restrict__ e0, const int* __restrict__ e1, int* cnt){
    int e = blockIdx.x*256 + threadIdx.x;
    if (e < E_EDGES){
        atomicAdd(&cnt[e0[e]], 1);
        atomicAdd(&cnt[e1[e]], 1);
    }
}
// ---------------- #3: scan ----------------
__global__ void k_scan(const int* __restrict__ cnt, int* __restrict__ rowptr,
                       int* __restrict__ rowcur, float* __restrict__ dis){
    __shared__ int sh[1024];
    int t = threadIdx.x;
    const int CH = (N_POI + 1023)/1024;
    int base = t*CH;
    int s = 0;
    for (int i = 0; i < CH; i++){
        int idx = base + i;
        if (idx < N_POI) s += cnt[idx];
    }
    sh[t] = s;
    __syncthreads();
    for (int o = 1; o < 1024; o <<= 1){
        int v = (t >= o) ? sh[t-o] : 0;
        __syncthreads();
        sh[t] += v;
        __syncthreads();
    }
    int off = (t == 0) ? 0 : sh[t-1];
    for (int i = 0; i < CH; i++){
        int idx = base + i;
        if (idx < N_POI){
            int c = cnt[idx];
            rowptr[idx] = off;
            rowcur[idx] = off;
            dis[idx] = rsqrtf((float)(c + 1));
            off += c;
        }
    }
    if (t == 1023) rowptr[N_POI] = sh[1023];
}
// ---------------- #4: scatter ----------------
__global__ void k_scatter(const int* __restrict__ e0, const int* __restrict__ e1,
                          const float* __restrict__ dv, const float* __restrict__ dis,
                          int* rowcur, int* __restrict__ colidx, float* __restrict__ wcsr){
    int e = blockIdx.x*256 + threadIdx.x;
    if (e >= E_EDGES) return;
    int a = e0[e], b = e1[e];
    float d = dv[e];
    float wv = expf(-d*d) * dis[a] * dis[b];
    int p = atomicAdd(&rowcur[a], 1);
    colidx[p] = b; wcsr[p] = wv;
    p = atomicAdd(&rowcur[b], 1);
    colidx[p] = a; wcsr[p] = wv;
}

// ---------------- #5: SpMM (R7 proven: scalar idx loads, fp16 gather) ----------------
__global__ void k_spmm2(const uint2* __restrict__ encH2, const int* __restrict__ rowptr,
                        const int* __restrict__ cols, const float* __restrict__ ws,
                        const float* __restrict__ dis, float4* __restrict__ agg4){
    int row = blockIdx.x*8 + (threadIdx.x >> 5);
    int lane = threadIdx.x & 31;
    if (row >= N_POI) return;
    float ds = dis[row];
    float sl = ds*ds;

    uint2 xs = encH2[row*32 + lane];
    float2 xa = __half22float2(*(const __half2*)&xs.x);
    float2 xb = __half22float2(*(const __half2*)&xs.y);
    float4 acc = make_float4(sl*xa.x, sl*xa.y, sl*xb.x, sl*xb.y);

    int s = __ldg(&rowptr[row]), e = __ldg(&rowptr[row+1]);
    int i = s;
    for (; i + 4 <= e; i += 4){
        int c0 = __ldg(&cols[i]),   c1 = __ldg(&cols[i+1]);
        int c2 = __ldg(&cols[i+2]), c3 = __ldg(&cols[i+3]);
        float w0 = __ldg(&ws[i]),   w1 = __ldg(&ws[i+1]);
        float w2 = __ldg(&ws[i+2]), w3 = __ldg(&ws[i+3]);
        uint2 u0 = encH2[c0*32 + lane];
        uint2 u1 = encH2[c1*32 + lane];
        uint2 u2 = encH2[c2*32 + lane];
        uint2 u3 = encH2[c3*32 + lane];
        float2 a0 = __half22float2(*(const __half2*)&u0.x), b0 = __half22float2(*(const __half2*)&u0.y);
        float2 a1 = __half22float2(*(const __half2*)&u1.x), b1 = __half22float2(*(const __half2*)&u1.y);
        float2 a2 = __half22float2(*(const __half2*)&u2.x), b2 = __half22float2(*(const __half2*)&u2.y);
        float2 a3 = __half22float2(*(const __half2*)&u3.x), b3 = __half22float2(*(const __half2*)&u3.y);
        acc.x = fmaf(w3,a3.x, fmaf(w2,a2.x, fmaf(w1,a1.x, fmaf(w0,a0.x, acc.x))));
        acc.y = fmaf(w3,a3.y, fmaf(w2,a2.y, fmaf(w1,a1.y, fmaf(w0,a0.y, acc.y))));
        acc.z = fmaf(w3,b3.x, fmaf(w2,b2.x, fmaf(w1,b1.x, fmaf(w0,b0.x, acc.z))));
        acc.w = fmaf(w3,b3.y, fmaf(w2,b2.y, fmaf(w1,b1.y, fmaf(w0,b0.y, acc.w))));
    }
    for (; i < e; i++){
        int c = __ldg(&cols[i]);
        float wv = __ldg(&ws[i]);
        uint2 u = encH2[c*32 + lane];
        float2 a = __half22float2(*(const __half2*)&u.x);
        float2 b = __half22float2(*(const __half2*)&u.y);
        acc.x = fmaf(wv, a.x, acc.x);
        acc.y = fmaf(wv, a.y, acc.y);
        acc.z = fmaf(wv, b.x, acc.z);
        acc.w = fmaf(wv, b.y, acc.w);
    }
    agg4[row*32 + lane] = acc;
}

// ---------------- #6 (ncu capture slot): tf32 GEMM + lrelu + row L2-norm ----------------
#define GP 132
__global__ void __launch_bounds__(256, 1)
k_gemm_tf32(const float4* __restrict__ X4, const float* __restrict__ W,
            const float* __restrict__ bias, float* __restrict__ Y,
            __half2* __restrict__ Yh2, int M, int write_f32){
    extern __shared__ uint32_t sh[];
    uint32_t* As = sh;
    uint32_t* Bs = sh + 128*GP;
    __shared__ float ssred[128][4];
    __shared__ float sscale[128];
    int tid = threadIdx.x;
    int row0 = blockIdx.x * 128;

    const float4* W4 = (const float4*)W;
    for (int i = tid; i < 128*32; i += 256){
        int r = i >> 5, c4 = i & 31;
        int grow = row0 + r;
        float4 v = (grow < M) ? X4[grow*32 + c4] : make_float4(0.f,0.f,0.f,0.f);
        float4 wv = W4[i];
        int base = r*GP + c4*4;
        uint4 av = make_uint4(to_tf32(v.x),  to_tf32(v.y),  to_tf32(v.z),  to_tf32(v.w));
        uint4 bv = make_uint4(to_tf32(wv.x), to_tf32(wv.y), to_tf32(wv.z), to_tf32(wv.w));
        *(uint4*)&As[base] = av;
        *(uint4*)&Bs[base] = bv;
    }
    __syncthreads();

    int wid = tid >> 5, lane = tid & 31;
    int wm = wid & 1, wn = wid >> 1;
    int m_base = wm*64, n_base = wn*32;
    int qr = lane >> 2, qc = lane & 3;

    float acc[4][4][4];
    #pragma unroll
    for (int mi = 0; mi < 4; mi++)
        #pragma unroll
        for (int ni = 0; ni < 4; ni++)
            #pragma unroll
            for (int j = 0; j < 4; j++) acc[mi][ni][j] = 0.f;

    #pragma unroll 2
    for (int k0 = 0; k0 < 128; k0 += 8){
        uint32_t a[4][4];
        #pragma unroll
        for (int mi = 0; mi < 4; mi++){
            const uint32_t* ap = As + (m_base + mi*16 + qr)*GP + k0 + qc;
            a[mi][0] = ap[0];
            a[mi][1] = ap[8*GP];
            a[mi][2] = ap[4];
            a[mi][3] = ap[8*GP + 4];
        }
        uint32_t b[4][2];
        #pragma unroll
        for (int ni = 0; ni < 4; ni++){
            const uint32_t* bp = Bs + (n_base + ni*8 + qr)*GP + k0 + qc;
            b[ni][0] = bp[0];
            b[ni][1] = bp[4];
        }
        #pragma unroll
        for (int mi = 0; mi < 4; mi++)
            #pragma unroll
            for (int ni = 0; ni < 4; ni++)
                mma_tf32(acc[mi][ni], a[mi], b[ni]);
    }

    float2 bv[4];
    #pragma unroll
    for (int ni = 0; ni < 4; ni++)
        bv[ni] = *(const float2*)&bias[n_base + ni*8 + qc*2];

    float ss[4][2];
    #pragma unroll
    for (int mi = 0; mi < 4; mi++){ ss[mi][0] = 0.f; ss[mi][1] = 0.f; }
    #pragma unroll
    for (int mi = 0; mi < 4; mi++)
        #pragma unroll
        for (int ni = 0; ni < 4; ni++){
            float* d = acc[mi][ni];
            float t0 = d[0] + bv[ni].x, t1 = d[1] + bv[ni].y;
            float t2 = d[2] + bv[ni].x, t3 = d[3] + bv[ni].y;
            t0 = (t0 >= 0.f) ? t0 : 0.01f*t0;
            t1 = (t1 >= 0.f) ? t1 : 0.01f*t1;
            t2 = (t2 >= 0.f) ? t2 : 0.01f*t2;
            t3 = (t3 >= 0.f) ? t3 : 0.01f*t3;
            d[0] = t0; d[1] = t1; d[2] = t2; d[3] = t3;
            ss[mi][0] = fmaf(t0,t0, fmaf(t1,t1, ss[mi][0]));
            ss[mi][1] = fmaf(t2,t2, fmaf(t3,t3, ss[mi][1]));
        }
    #pragma unroll
    for (int mi = 0; mi < 4; mi++)
        #pragma unroll
        for (int hf = 0; hf < 2; hf++){
            float v = ss[mi][hf];
            v += __shfl_xor_sync(0xffffffffu, v, 1);
            v += __shfl_xor_sync(0xffffffffu, v, 2);
            if (qc == 0) ssred[m_base + mi*16 + qr + hf*8][wn] = v;
        }
    __syncthreads();
    if (tid < 128){
        float t = ssred[tid][0] + ssred[tid][1] + ssred[tid][2] + ssred[tid][3];
        sscale[tid] = 1.0f / fmaxf(sqrtf(t), 1e-12f);
    }
    __syncthreads();

    #pragma unroll
    for (int mi = 0; mi < 4; mi++){
        int lr0 = m_base + mi*16 + qr;
        int lr1 = lr0 + 8;
        float s0 = sscale[lr0], s1 = sscale[lr1];
        int r0 = row0 + lr0, r1 = row0 + lr1;
        #pragma unroll
        for (int ni = 0; ni < 4; ni++){
            float* d = acc[mi][ni];
            int col = n_base + ni*8 + qc*2;
            if (r0 < M){
                float y0 = d[0]*s0, y1 = d[1]*s0;
                if (write_f32) *(float2*)&Y[r0*DIM + col] = make_float2(y0, y1);
                Yh2[r0*64 + (col >> 1)] = __floats2half2_rn(y0, y1);
            }
            if (r1 < M){
                float y2 = d[2]*s1, y3 = d[3]*s1;
                if (write_f32) *(float2*)&Y[r1*DIM + col] = make_float2(y2, y3);
                Yh2[r1*64 + (col >> 1)] = __floats2half2_rn(y2, y3);
            }
        }
    }
}

// ---------------- QKV: scalar tiled GEMM ----------------
__global__ void __launch_bounds__(256, 1)
k_qkv2(const float4* __restrict__ enc4, const int* __restrict__ xidx,
       const float* __restrict__ inw, const float* __restrict__ inb,
       float4* __restrict__ qkv4){
    extern __shared__ float4 sh4[];
    float4* Xs = sh4;
    float4* Ws = sh4 + 4096;
    int tid = threadIdx.x;
    int row0 = blockIdx.x * 128;
    int nb = blockIdx.y;
    #pragma unroll
    for (int it = 0; it < 16; it++){
        int idx = tid + it*256;
        int m = idx >> 5, k4 = idx & 31;
        int src = __ldg(&xidx[row0 + m]);
        Xs[idx] = enc4[src*32 + k4];
    }
    const float4* W4 = (const float4*)(inw + nb*DIM*DIM);
    #pragma unroll
    for (int it = 0; it < 16; it++){
        int idx = tid + it*256;
        int n = idx >> 5, k4 = idx & 31;
        Ws[n*32 + (k4 ^ (n >> 3))] = W4[idx];
    }
    __syncthreads();

    int tx = tid & 15, ty = tid >> 4;
    float acc[8][8];
    #pragma unroll
    for (int r = 0; r < 8; r++)
        #pragma unroll
        for (int c = 0; c < 8; c++) acc[r][c] = 0.f;

    const float4* Xp = Xs + (ty*8)*32;
    const float4* Wp = Ws + (tx*8)*32;
    #pragma unroll 2
    for (int k4 = 0; k4 < 32; k4++){
        float4 xv[8], wv[8];
        #pragma unroll
        for (int r = 0; r < 8; r++) xv[r] = Xp[r*32 + k4];
        int ksw = k4 ^ tx;
        #pragma unroll
        for (int c = 0; c < 8; c++) wv[c] = Wp[c*32 + ksw];
        #pragma unroll
        for (int r = 0; r < 8; r++)
            #pragma unroll
            for (int c = 0; c < 8; c++){
                acc[r][c] = fmaf(xv[r].x, wv[c].x, acc[r][c]);
                acc[r][c] = fmaf(xv[r].y, wv[c].y, acc[r][c]);
                acc[r][c] = fmaf(xv[r].z, wv[c].z, acc[r][c]);
                acc[r][c] = fmaf(xv[r].w, wv[c].w, acc[r][c]);
            }
    }

    float bj[8];
    #pragma unroll
    for (int c = 0; c < 8; c++) bj[c] = __ldg(&inb[nb*DIM + tx*8 + c]);
    #pragma unroll
    for (int r = 0; r < 8; r++){
        int t = row0 + ty*8 + r;
        qkv4[t*96 + nb*32 + tx*2]     = make_float4(acc[r][0]+bj[0], acc[r][1]+bj[1], acc[r][2]+bj[2], acc[r][3]+bj[3]);
        qkv4[t*96 + nb*32 + tx*2 + 1] = make_float4(acc[r][4]+bj[4], acc[r][5]+bj[5], acc[r][6]+bj[6], acc[r][7]+bj[7]);
    }
}

// ---------------- attention: conflict-free, one block per (b, h) ----------------
__global__ void k_attn(const float* __restrict__ qkv, float* __restrict__ o){
    extern __shared__ float sha[];
    float* sq  = sha;
    float* skT = sha + LSEQ*16;
    float* sv  = sha + 2*LSEQ*16;
    float* sp  = sha + 3*LSEQ*16;
    int b = blockIdx.x, h = blockIdx.y;
    int tid = threadIdx.x;
    for (int idx = tid; idx < LSEQ*16; idx += 128){
        int t = idx >> 4, d = idx & 15;
        int base = (b*LSEQ + t)*(3*DIM) + h*16 + d;
        sq[idx] = qkv[base];
        sv[idx] = qkv[base + 2*DIM];
    }
    for (int idx = tid; idx < LSEQ*16; idx += 128){
        int d = idx / LSEQ, t = idx - d*LSEQ;
        skT[idx] = qkv[(b*LSEQ + t)*(3*DIM) + DIM + h*16 + d];
    }
    __syncthreads();

    int lane = tid & 31, warp = tid >> 5;
    for (int qi = warp; qi < LSEQ; qi += 4){
        float q[16];
        #pragma unroll
        for (int d = 0; d < 16; d++) q[d] = sq[qi*16 + d];
        float v[4];
        float m = -1e30f;
        #pragma unroll
        for (int g = 0; g < 4; g++){
            int j = lane + g*32;
            float s = -1e30f;
            if (j < LSEQ){
                s = 0.f;
                #pragma unroll
                for (int d = 0; d < 16; d++) s = fmaf(q[d], skT[d*LSEQ + j], s);
                s *= 0.25f;
            }
            v[g] = s;
            m = fmaxf(m, s);
        }
        #pragma unroll
        for (int t = 16; t > 0; t >>= 1) m = fmaxf(m, __shfl_xor_sync(0xffffffffu, m, t));
        float ssum = 0.f;
        #pragma unroll
        for (int g = 0; g < 4; g++){
            int j = lane + g*32;
            float p = (j < LSEQ) ? __expf(v[g] - m) : 0.f;
            v[g] = p;
            ssum += p;
        }
        #pragma unroll
        for (int t = 16; t > 0; t >>= 1) ssum += __shfl_xor_sync(0xffffffffu, ssum, t);
        float inv = 1.0f / ssum;
        #pragma unroll
        for (int g = 0; g < 4; g++){
            int j = lane + g*32;
            if (j < LSEQ) sp[qi*LSEQ + j] = v[g]*inv;
        }
    }
    __syncthreads();

    const float4* sv4 = (const float4*)sv;
    for (int u = tid; u < LSEQ*4; u += 128){
        int qi = u >> 2, dg = u & 3;
        float4 acc = make_float4(0.f,0.f,0.f,0.f);
        const float* pp = sp + qi*LSEQ;
        #pragma unroll 4
        for (int j = 0; j < LSEQ; j++){
            float p = pp[j];
            float4 vv = sv4[j*4 + dg];
            acc.x = fmaf(p, vv.x, acc.x);
            acc.y = fmaf(p, vv.y, acc.y);
            acc.z = fmaf(p, vv.z, acc.z);
            acc.w = fmaf(p, vv.w, acc.w);
        }
        *(float4*)&o[(b*LSEQ + qi)*DIM + h*16 + dg*4] = acc;
    }
}

// ---------------- mean over L + out-projection + target gather ----------------
__global__ void k_tail(const float* __restrict__ o, const float* __restrict__ ow,
                       const float* __restrict__ ob, const float* __restrict__ enc,
                       const int* __restrict__ pidx, float* __restrict__ out){
    __shared__ float sx[DIM];
    int b = blockIdx.x, j = threadIdx.x;
    float s = 0.0f;
    for (int i = 0; i < LSEQ; i++) s += o[(b*LSEQ + i)*DIM + j];
    sx[j] = s * (1.0f/LSEQ);
    __syncthreads();
    float acc = ob[j];
    #pragma unroll 4
    for (int k = 0; k < DIM; k++) acc += sx[k]*ow[j*DIM + k];
    out[b*DIM + j] = acc;
    out[BATCH*DIM + b*DIM + j] = enc[pidx[b]*DIM + j];
}

// ---------------- host launch ----------------
extern "C" void kernel_launch(void* const* d_in, const int* in_sizes, int n_in,
                              void* d_out, int out_size){
    const float* embeds = (const float*)d_in[0];
    const float* gcnW   = (const float*)d_in[1];
    const float* gcnb   = (const float*)d_in[2];
    const float* inw    = (const float*)d_in[3];
    const float* inb    = (const float*)d_in[4];
    const float* ow     = (const float*)d_in[5];
    const float* ob     = (const float*)d_in[6];
    const float* dv     = (const float*)d_in[7];
    const int*   edges  = (const int*)d_in[8];
    const int*   xidx   = (const int*)d_in[9];
    const int*   pidx   = (const int*)d_in[10];
    const int* e0 = edges;
    const int* e1 = edges + E_EDGES;
    float* out = (float*)d_out;

    int *cnt, *rowptr, *rowcur, *colidx;
    float *dis, *wcsr, *agg, *bA, *qkv, *obuf;
    __half* encH;
    cudaGetSymbolAddress((void**)&cnt,    g_cnt);
    cudaGetSymbolAddress((void**)&rowptr, g_rowptr);
    cudaGetSymbolAddress((void**)&rowcur, g_rowcur);
    cudaGetSymbolAddress((void**)&dis,    g_dis);
    cudaGetSymbolAddress((void**)&colidx, g_colidx);
    cudaGetSymbolAddress((void**)&wcsr,   g_wcsr);
    cudaGetSymbolAddress((void**)&agg,    g_agg);
    cudaGetSymbolAddress((void**)&bA,     g_bufA);
    cudaGetSymbolAddress((void**)&encH,   g_encH);
    cudaGetSymbolAddress((void**)&qkv,    g_qkv);
    cudaGetSymbolAddress((void**)&obuf,   g_o);

    const int smem_qkv  = 2*4096*(int)sizeof(float4);
    const int smem_gemm = 2*128*GP*(int)sizeof(uint32_t);
    const int smem_attn = (3*LSEQ*16 + LSEQ*LSEQ)*(int)sizeof(float);
    cudaFuncSetAttribute(k_gemm_tf32, cudaFuncAttributeMaxDynamicSharedMemorySize, smem_gemm);
    cudaFuncSetAttribute(k_qkv2,      cudaFuncAttributeMaxDynamicSharedMemorySize, smem_qkv);
    cudaFuncSetAttribute(k_attn,      cudaFuncAttributeMaxDynamicSharedMemorySize, smem_attn);

    // launch order: cvt(1) hist(2) scan(3) scatter(4) spmm(5) gemm(6 <- ncu slot)
    cudaMemsetAsync(cnt, 0, N_POI*sizeof(int));     // memset node: not counted by ncu skip
    k_cvt_h<<<(N_POI*32+255)/256, 256>>>((const float4*)embeds, (__half2*)encH, N_POI*32);
    k_hist<<<(E_EDGES+255)/256, 256>>>(e0, e1, cnt);
    k_scan<<<1, 1024>>>(cnt, rowptr, rowcur, dis);
    k_scatter<<<(E_EDGES+255)/256, 256>>>(e0, e1, dv, dis, rowcur, colidx, wcsr);

    // 3 GCN layers; fp32 output only needed after the last layer
    for (int i = 0; i < GCN_NUM; i++){
        k_spmm2<<<(N_POI+7)/8, 256>>>((const uint2*)encH, rowptr, colidx, wcsr, dis,
                                       (float4*)agg);
        k_gemm_tf32<<<(N_POI+127)/128, 256, smem_gemm>>>(
            (const float4*)agg, gcnW + i*DIM*DIM, gcnb + i*DIM, bA, (__half2*)encH,
            N_POI, (i == GCN_NUM-1) ? 1 : 0);
    }
    const float* encF = bA;

    // attention
    k_qkv2<<<dim3(NTOK/128, 3), 256, smem_qkv>>>((const float4*)encF, xidx, inw, inb,
                                                 (float4*)qkv);
    k_attn<<<dim3(BATCH, 8), 128, smem_attn>>>(qkv, obuf);
    k_tail<<<BATCH, 128>>>(obuf, ow, ob, encF, pidx, out);
}

// round 10
// speedup vs baseline: 1.1895x; 1.1216x over previous
#include <cuda_runtime.h>
#include <cuda_fp16.h>
#include <math.h>
#include <stdint.h>

#define N_POI 50000
#define DIM 128
#define E_EDGES 400000
#define GCN_NUM 3
#define BATCH 64
#define LSEQ 100
#define NTOK (BATCH*LSEQ)
#define DIRE (2*E_EDGES)

// ---------------- device scratch ----------------
__device__ __align__(16) int    g_cnt[N_POI];
__device__ __align__(16) int    g_rowptr[N_POI+1];
__device__ __align__(16) int    g_rowcur[N_POI];
__device__ __align__(16) float  g_dis[N_POI];
__device__ __align__(16) int    g_colidx[DIRE];
__device__ __align__(16) float  g_wcsr[DIRE];
__device__ __align__(16) float  g_bufA[N_POI*DIM];
__device__ __align__(16) __half g_aggH[N_POI*DIM];   // SpMM output, fp16
__device__ __align__(16) __half g_encH[N_POI*DIM];   // enc mirror, fp16
__device__ __align__(16) __half g_WH[GCN_NUM*DIM*DIM]; // gcn weights, fp16
__device__ __align__(16) float  g_qkv[NTOK*3*DIM];
__device__ __align__(16) float  g_o[NTOK*DIM];

// fp16 HMMA m16n8k16, fp32 accumulate
__device__ __forceinline__ void mma_f16(float* d, const uint32_t* a, const uint32_t* b){
    asm volatile("mma.sync.aligned.m16n8k16.row.col.f32.f16.f16.f32 "
        "{%0,%1,%2,%3}, {%4,%5,%6,%7}, {%8,%9}, {%0,%1,%2,%3};"
        : "+f"(d[0]), "+f"(d[1]), "+f"(d[2]), "+f"(d[3])
        : "r"(a[0]), "r"(a[1]), "r"(a[2]), "r"(a[3]), "r"(b[0]), "r"(b[1]));
}

// ---------------- #1: hist + fp16 converts (embeds + gcn weights) ----------------
__global__ void k_hist_cvt(const int* __restrict__ e0, const int* __restrict__ e1,
                           int* cnt, const float4* __restrict__ emb4,
                           const float4* __restrict__ w4,
                           __half2* __restrict__ encH2, __half2* __restrict__ WH2){
    int i = blockIdx.x*256 + threadIdx.x;
    if (i < E_EDGES){
        atomicAdd(&cnt[e0[i]], 1);
        atomicAdd(&cnt[e1[i]], 1);
    }
    const int NE4 = N_POI*32;
    const int NW4 = GCN_NUM*DIM*32;
    for (int j = i; j < NE4 + NW4; j += gridDim.x*256){
        if (j < NE4){
            float4 v = emb4[j];
            encH2[j*2]     = __floats2half2_rn(v.x, v.y);
            encH2[j*2 + 1] = __floats2half2_rn(v.z, v.w);
        } else {
            int k = j - NE4;
            float4 v = w4[k];
            WH2[k*2]     = __floats2half2_rn(v.x, v.y);
            WH2[k*2 + 1] = __floats2half2_rn(v.z, v.w);
        }
    }
}
// ---------------- #2: scan ----------------
__global__ void k_scan(const int* __restrict__ cnt, int* __restrict__ rowptr,
                       int* __restrict__ rowcur, float* __restrict__ dis){
    __shared__ int sh[1024];
    int t = threadIdx.x;
    const int CH = (N_POI + 1023)/1024;
    int base = t*CH;
    int s = 0;
    for (int i = 0; i < CH; i++){
        int idx = base + i;
        if (idx < N_POI) s += cnt[idx];
    }
    sh[t] = s;
    __syncthreads();
    for (int o = 1; o < 1024; o <<= 1){
        int v = (t >= o) ? sh[t-o] : 0;
        __syncthreads();
        sh[t] += v;
        __syncthreads();
    }
    int off = (t == 0) ? 0 : sh[t-1];
    for (int i = 0; i < CH; i++){
        int idx = base + i;
        if (idx < N_POI){
            int c = cnt[idx];
            rowptr[idx] = off;
            rowcur[idx] = off;
            dis[idx] = rsqrtf((float)(c + 1));
            off += c;
        }
    }
    if (t == 1023) rowptr[N_POI] = sh[1023];
}
// ---------------- #3: scatter ----------------
__global__ void k_scatter(const int* __restrict__ e0, const int* __restrict__ e1,
                          const float* __restrict__ dv, const float* __restrict__ dis,
                          int* rowcur, int* __restrict__ colidx, float* __restrict__ wcsr){
    int e = blockIdx.x*256 + threadIdx.x;
    if (e >= E_EDGES) return;
    int a = e0[e], b = e1[e];
    float d = dv[e];
    float wv = expf(-d*d) * dis[a] * dis[b];
    int p = atomicAdd(&rowcur[a], 1);
    colidx[p] = b; wcsr[p] = wv;
    p = atomicAdd(&rowcur[b], 1);
    colidx[p] = a; wcsr[p] = wv;
}

// ---------------- #4 (ncu slot): SpMM fp16 gather -> fp16 agg ----------------
__global__ void k_spmm2(const uint2* __restrict__ encH2, const int* __restrict__ rowptr,
                        const int* __restrict__ cols, const float* __restrict__ ws,
                        const float* __restrict__ dis, uint2* __restrict__ aggH2){
    int row = blockIdx.x*8 + (threadIdx.x >> 5);
    int lane = threadIdx.x & 31;
    if (row >= N_POI) return;
    float ds = dis[row];
    float sl = ds*ds;

    uint2 xs = encH2[row*32 + lane];
    float2 xa = __half22float2(*(const __half2*)&xs.x);
    float2 xb = __half22float2(*(const __half2*)&xs.y);
    float4 acc = make_float4(sl*xa.x, sl*xa.y, sl*xb.x, sl*xb.y);

    int s = __ldg(&rowptr[row]), e = __ldg(&rowptr[row+1]);
    int i = s;
    for (; i + 4 <= e; i += 4){
        int c0 = __ldg(&cols[i]),   c1 = __ldg(&cols[i+1]);
        int c2 = __ldg(&cols[i+2]), c3 = __ldg(&cols[i+3]);
        float w0 = __ldg(&ws[i]),   w1 = __ldg(&ws[i+1]);
        float w2 = __ldg(&ws[i+2]), w3 = __ldg(&ws[i+3]);
        uint2 u0 = encH2[c0*32 + lane];
        uint2 u1 = encH2[c1*32 + lane];
        uint2 u2 = encH2[c2*32 + lane];
        uint2 u3 = encH2[c3*32 + lane];
        float2 a0 = __half22float2(*(const __half2*)&u0.x), b0 = __half22float2(*(const __half2*)&u0.y);
        float2 a1 = __half22float2(*(const __half2*)&u1.x), b1 = __half22float2(*(const __half2*)&u1.y);
        float2 a2 = __half22float2(*(const __half2*)&u2.x), b2 = __half22float2(*(const __half2*)&u2.y);
        float2 a3 = __half22float2(*(const __half2*)&u3.x), b3 = __half22float2(*(const __half2*)&u3.y);
        acc.x = fmaf(w3,a3.x, fmaf(w2,a2.x, fmaf(w1,a1.x, fmaf(w0,a0.x, acc.x))));
        acc.y = fmaf(w3,a3.y, fmaf(w2,a2.y, fmaf(w1,a1.y, fmaf(w0,a0.y, acc.y))));
        acc.z = fmaf(w3,b3.x, fmaf(w2,b2.x, fmaf(w1,b1.x, fmaf(w0,b0.x, acc.z))));
        acc.w = fmaf(w3,b3.y, fmaf(w2,b2.y, fmaf(w1,b1.y, fmaf(w0,b0.y, acc.w))));
    }
    for (; i < e; i++){
        int c = __ldg(&cols[i]);
        float wv = __ldg(&ws[i]);
        uint2 u = encH2[c*32 + lane];
        float2 a = __half22float2(*(const __half2*)&u.x);
        float2 b = __half22float2(*(const __half2*)&u.y);
        acc.x = fmaf(wv, a.x, acc.x);
        acc.y = fmaf(wv, a.y, acc.y);
        acc.z = fmaf(wv, b.x, acc.z);
        acc.w = fmaf(wv, b.y, acc.w);
    }
    uint2 o;
    *(__half2*)&o.x = __floats2half2_rn(acc.x, acc.y);
    *(__half2*)&o.y = __floats2half2_rn(acc.z, acc.w);
    aggH2[row*32 + lane] = o;
}

// ---------------- #5: fp16 HMMA GEMM + lrelu + row L2-norm ----------------
#define PH 136   // smem pitch in halves (conflict-free frags)
__global__ void __launch_bounds__(256, 2)
k_gemm_h(const uint2* __restrict__ aggH2, const uint2* __restrict__ WH2,
         const float* __restrict__ bias, float* __restrict__ Y,
         __half2* __restrict__ Yh2, int M, int write_f32){
    extern __shared__ __half shh[];
    __half* As = shh;            // [128][PH]
    __half* Bs = shh + 128*PH;   // [128][PH]
    __shared__ float ssred[128][4];
    __shared__ float sscale[128];
    int tid = threadIdx.x;
    int row0 = blockIdx.x * 128;

    // stage: pure fp16 copies (agg + weights already fp16)
    for (int i = tid; i < 128*32; i += 256){
        int r = i >> 5, c8 = i & 31;
        int grow = row0 + r;
        uint2 av = (grow < M) ? aggH2[grow*32 + c8] : make_uint2(0u, 0u);
        *(uint2*)&As[r*PH + c8*4] = av;
        *(uint2*)&Bs[r*PH + c8*4] = WH2[i];
    }
    __syncthreads();

    int wid = tid >> 5, lane = tid & 31;
    int wm = wid & 1, wn = wid >> 1;
    int m_base = wm*64, n_base = wn*32;
    int qr = lane >> 2, qc = lane & 3;

    float acc[4][4][4];
    #pragma unroll
    for (int mi = 0; mi < 4; mi++)
        #pragma unroll
        for (int ni = 0; ni < 4; ni++)
            #pragma unroll
            for (int j = 0; j < 4; j++) acc[mi][ni][j] = 0.f;

    #pragma unroll
    for (int k0 = 0; k0 < 128; k0 += 16){
        uint32_t a[4][4];
        #pragma unroll
        for (int mi = 0; mi < 4; mi++){
            const __half* ap = As + (m_base + mi*16 + qr)*PH + k0 + 2*qc;
            a[mi][0] = *(const uint32_t*)ap;
            a[mi][1] = *(const uint32_t*)(ap + 8*PH);
            a[mi][2] = *(const uint32_t*)(ap + 8);
            a[mi][3] = *(const uint32_t*)(ap + 8*PH + 8);
        }
        uint32_t b[4][2];
        #pragma unroll
        for (int ni = 0; ni < 4; ni++){
            const __half* bp = Bs + (n_base + ni*8 + qr)*PH + k0 + 2*qc;
            b[ni][0] = *(const uint32_t*)bp;
            b[ni][1] = *(const uint32_t*)(bp + 8);
        }
        #pragma unroll
        for (int mi = 0; mi < 4; mi++)
            #pragma unroll
            for (int ni = 0; ni < 4; ni++)
                mma_f16(acc[mi][ni], a[mi], b[ni]);
    }

    float2 bv[4];
    #pragma unroll
    for (int ni = 0; ni < 4; ni++)
        bv[ni] = *(const float2*)&bias[n_base + ni*8 + qc*2];

    float ss[4][2];
    #pragma unroll
    for (int mi = 0; mi < 4; mi++){ ss[mi][0] = 0.f; ss[mi][1] = 0.f; }
    #pragma unroll
    for (int mi = 0; mi < 4; mi++)
        #pragma unroll
        for (int ni = 0; ni < 4; ni++){
            float* d = acc[mi][ni];
            float t0 = d[0] + bv[ni].x, t1 = d[1] + bv[ni].y;
            float t2 = d[2] + bv[ni].x, t3 = d[3] + bv[ni].y;
            t0 = (t0 >= 0.f) ? t0 : 0.01f*t0;
            t1 = (t1 >= 0.f) ? t1 : 0.01f*t1;
            t2 = (t2 >= 0.f) ? t2 : 0.01f*t2;
            t3 = (t3 >= 0.f) ? t3 : 0.01f*t3;
            d[0] = t0; d[1] = t1; d[2] = t2; d[3] = t3;
            ss[mi][0] = fmaf(t0,t0, fmaf(t1,t1, ss[mi][0]));
            ss[mi][1] = fmaf(t2,t2, fmaf(t3,t3, ss[mi][1]));
        }
    #pragma unroll
    for (int mi = 0; mi < 4; mi++)
        #pragma unroll
        for (int hf = 0; hf < 2; hf++){
            float v = ss[mi][hf];
            v += __shfl_xor_sync(0xffffffffu, v, 1);
            v += __shfl_xor_sync(0xffffffffu, v, 2);
            if (qc == 0) ssred[m_base + mi*16 + qr + hf*8][wn] = v;
        }
    __syncthreads();
    if (tid < 128){
        float t = ssred[tid][0] + ssred[tid][1] + ssred[tid][2] + ssred[tid][3];
        sscale[tid] = 1.0f / fmaxf(sqrtf(t), 1e-12f);
    }
    __syncthreads();

    #pragma unroll
    for (int mi = 0; mi < 4; mi++){
        int lr0 = m_base + mi*16 + qr;
        int lr1 = lr0 + 8;
        float s0 = sscale[lr0], s1 = sscale[lr1];
        int r0 = row0 + lr0, r1 = row0 + lr1;
        #pragma unroll
        for (int ni = 0; ni < 4; ni++){
            float* d = acc[mi][ni];
            int col = n_base + ni*8 + qc*2;
            if (r0 < M){
                float y0 = d[0]*s0, y1 = d[1]*s0;
                if (write_f32) *(float2*)&Y[r0*DIM + col] = make_float2(y0, y1);
                Yh2[r0*64 + (col >> 1)] = __floats2half2_rn(y0, y1);
            }
            if (r1 < M){
                float y2 = d[2]*s1, y3 = d[3]*s1;
                if (write_f32) *(float2*)&Y[r1*DIM + col] = make_float2(y2, y3);
                Yh2[r1*64 + (col >> 1)] = __floats2half2_rn(y2, y3);
            }
        }
    }
}

// ---------------- QKV: scalar tiled GEMM ----------------
__global__ void __launch_bounds__(256, 1)
k_qkv2(const float4* __restrict__ enc4, const int* __restrict__ xidx,
       const float* __restrict__ inw, const float* __restrict__ inb,
       float4* __restrict__ qkv4){
    extern __shared__ float4 sh4[];
    float4* Xs = sh4;
    float4* Ws = sh4 + 4096;
    int tid = threadIdx.x;
    int row0 = blockIdx.x * 128;
    int nb = blockIdx.y;
    #pragma unroll
    for (int it = 0; it < 16; it++){
        int idx = tid + it*256;
        int m = idx >> 5, k4 = idx & 31;
        int src = __ldg(&xidx[row0 + m]);
        Xs[idx] = enc4[src*32 + k4];
    }
    const float4* W4 = (const float4*)(inw + nb*DIM*DIM);
    #pragma unroll
    for (int it = 0; it < 16; it++){
        int idx = tid + it*256;
        int n = idx >> 5, k4 = idx & 31;
        Ws[n*32 + (k4 ^ (n >> 3))] = W4[idx];
    }
    __syncthreads();

    int tx = tid & 15, ty = tid >> 4;
    float acc[8][8];
    #pragma unroll
    for (int r = 0; r < 8; r++)
        #pragma unroll
        for (int c = 0; c < 8; c++) acc[r][c] = 0.f;

    const float4* Xp = Xs + (ty*8)*32;
    const float4* Wp = Ws + (tx*8)*32;
    #pragma unroll 2
    for (int k4 = 0; k4 < 32; k4++){
        float4 xv[8], wv[8];
        #pragma unroll
        for (int r = 0; r < 8; r++) xv[r] = Xp[r*32 + k4];
        int ksw = k4 ^ tx;
        #pragma unroll
        for (int c = 0; c < 8; c++) wv[c] = Wp[c*32 + ksw];
        #pragma unroll
        for (int r = 0; r < 8; r++)
            #pragma unroll
            for (int c = 0; c < 8; c++){
                acc[r][c] = fmaf(xv[r].x, wv[c].x, acc[r][c]);
                acc[r][c] = fmaf(xv[r].y, wv[c].y, acc[r][c]);
                acc[r][c] = fmaf(xv[r].z, wv[c].z, acc[r][c]);
                acc[r][c] = fmaf(xv[r].w, wv[c].w, acc[r][c]);
            }
    }

    float bj[8];
    #pragma unroll
    for (int c = 0; c < 8; c++) bj[c] = __ldg(&inb[nb*DIM + tx*8 + c]);
    #pragma unroll
    for (int r = 0; r < 8; r++){
        int t = row0 + ty*8 + r;
        qkv4[t*96 + nb*32 + tx*2]     = make_float4(acc[r][0]+bj[0], acc[r][1]+bj[1], acc[r][2]+bj[2], acc[r][3]+bj[3]);
        qkv4[t*96 + nb*32 + tx*2 + 1] = make_float4(acc[r][4]+bj[4], acc[r][5]+bj[5], acc[r][6]+bj[6], acc[r][7]+bj[7]);
    }
}

// ---------------- attention: conflict-free, one block per (b, h) ----------------
__global__ void k_attn(const float* __restrict__ qkv, float* __restrict__ o){
    extern __shared__ float sha[];
    float* sq  = sha;
    float* skT = sha + LSEQ*16;
    float* sv  = sha + 2*LSEQ*16;
    float* sp  = sha + 3*LSEQ*16;
    int b = blockIdx.x, h = blockIdx.y;
    int tid = threadIdx.x;
    for (int idx = tid; idx < LSEQ*16; idx += 128){
        int t = idx >> 4, d = idx & 15;
        int base = (b*LSEQ + t)*(3*DIM) + h*16 + d;
        sq[idx] = qkv[base];
        sv[idx] = qkv[base + 2*DIM];
    }
    for (int idx = tid; idx < LSEQ*16; idx += 128){
        int d = idx / LSEQ, t = idx - d*LSEQ;
        skT[idx] = qkv[(b*LSEQ + t)*(3*DIM) + DIM + h*16 + d];
    }
    __syncthreads();

    int lane = tid & 31, warp = tid >> 5;
    for (int qi = warp; qi < LSEQ; qi += 4){
        float q[16];
        #pragma unroll
        for (int d = 0; d < 16; d++) q[d] = sq[qi*16 + d];
        float v[4];
        float m = -1e30f;
        #pragma unroll
        for (int g = 0; g < 4; g++){
            int j = lane + g*32;
            float s = -1e30f;
            if (j < LSEQ){
                s = 0.f;
                #pragma unroll
                for (int d = 0; d < 16; d++) s = fmaf(q[d], skT[d*LSEQ + j], s);
                s *= 0.25f;
            }
            v[g] = s;
            m = fmaxf(m, s);
        }
        #pragma unroll
        for (int t = 16; t > 0; t >>= 1) m = fmaxf(m, __shfl_xor_sync(0xffffffffu, m, t));
        float ssum = 0.f;
        #pragma unroll
        for (int g = 0; g < 4; g++){
            int j = lane + g*32;
            float p = (j < LSEQ) ? __expf(v[g] - m) : 0.f;
            v[g] = p;
            ssum += p;
        }
        #pragma unroll
        for (int t = 16; t > 0; t >>= 1) ssum += __shfl_xor_sync(0xffffffffu, ssum, t);
        float inv = 1.0f / ssum;
        #pragma unroll
        for (int g = 0; g < 4; g++){
            int j = lane + g*32;
            if (j < LSEQ) sp[qi*LSEQ + j] = v[g]*inv;
        }
    }
    __syncthreads();

    const float4* sv4 = (const float4*)sv;
    for (int u = tid; u < LSEQ*4; u += 128){
        int qi = u >> 2, dg = u & 3;
        float4 acc = make_float4(0.f,0.f,0.f,0.f);
        const float* pp = sp + qi*LSEQ;
        #pragma unroll 4
        for (int j = 0; j < LSEQ; j++){
            float p = pp[j];
            float4 vv = sv4[j*4 + dg];
            acc.x = fmaf(p, vv.x, acc.x);
            acc.y = fmaf(p, vv.y, acc.y);
            acc.z = fmaf(p, vv.z, acc.z);
            acc.w = fmaf(p, vv.w, acc.w);
        }
        *(float4*)&o[(b*LSEQ + qi)*DIM + h*16 + dg*4] = acc;
    }
}

// ---------------- mean over L + out-projection + target gather ----------------
__global__ void k_tail(const float* __restrict__ o, const float* __restrict__ ow,
                       const float* __restrict__ ob, const float* __restrict__ enc,
                       const int* __restrict__ pidx, float* __restrict__ out){
    __shared__ float sx[DIM];
    int b = blockIdx.x, j = threadIdx.x;
    float s = 0.0f;
    for (int i = 0; i < LSEQ; i++) s += o[(b*LSEQ + i)*DIM + j];
    sx[j] = s * (1.0f/LSEQ);
    __syncthreads();
    float acc = ob[j];
    #pragma unroll 4
    for (int k = 0; k < DIM; k++) acc += sx[k]*ow[j*DIM + k];
    out[b*DIM + j] = acc;
    out[BATCH*DIM + b*DIM + j] = enc[pidx[b]*DIM + j];
}

// ---------------- host launch ----------------
extern "C" void kernel_launch(void* const* d_in, const int* in_sizes, int n_in,
                              void* d_out, int out_size){
    const float* embeds = (const float*)d_in[0];
    const float* gcnW   = (const float*)d_in[1];
    const float* gcnb   = (const float*)d_in[2];
    const float* inw    = (const float*)d_in[3];
    const float* inb    = (const float*)d_in[4];
    const float* ow     = (const float*)d_in[5];
    const float* ob     = (const float*)d_in[6];
    const float* dv     = (const float*)d_in[7];
    const int*   edges  = (const int*)d_in[8];
    const int*   xidx   = (const int*)d_in[9];
    const int*   pidx   = (const int*)d_in[10];
    const int* e0 = edges;
    const int* e1 = edges + E_EDGES;
    float* out = (float*)d_out;

    int *cnt, *rowptr, *rowcur, *colidx;
    float *dis, *wcsr, *bA, *qkv, *obuf;
    __half *encH, *aggH, *WH;
    cudaGetSymbolAddress((void**)&cnt,    g_cnt);
    cudaGetSymbolAddress((void**)&rowptr, g_rowptr);
    cudaGetSymbolAddress((void**)&rowcur, g_rowcur);
    cudaGetSymbolAddress((void**)&dis,    g_dis);
    cudaGetSymbolAddress((void**)&colidx, g_colidx);
    cudaGetSymbolAddress((void**)&wcsr,   g_wcsr);
    cudaGetSymbolAddress((void**)&bA,     g_bufA);
    cudaGetSymbolAddress((void**)&aggH,   g_aggH);
    cudaGetSymbolAddress((void**)&encH,   g_encH);
    cudaGetSymbolAddress((void**)&WH,     g_WH);
    cudaGetSymbolAddress((void**)&qkv,    g_qkv);
    cudaGetSymbolAddress((void**)&obuf,   g_o);

    const int smem_qkv  = 2*4096*(int)sizeof(float4);      // 131072
    const int smem_gemm = 2*128*PH*(int)sizeof(__half);    // 69632
    const int smem_attn = (3*LSEQ*16 + LSEQ*LSEQ)*(int)sizeof(float);
    cudaFuncSetAttribute(k_gemm_h, cudaFuncAttributeMaxDynamicSharedMemorySize, smem_gemm);
    cudaFuncSetAttribute(k_qkv2,   cudaFuncAttributeMaxDynamicSharedMemorySize, smem_qkv);
    cudaFuncSetAttribute(k_attn,   cudaFuncAttributeMaxDynamicSharedMemorySize, smem_attn);

    // launch order: hist_cvt(1) scan(2) scatter(3) spmm(4 <- ncu slot) gemm(5) ...
    cudaMemsetAsync(cnt, 0, N_POI*sizeof(int));
    k_hist_cvt<<<(N_POI*32+255)/256, 256>>>(e0, e1, cnt, (const float4*)embeds,
                                            (const float4*)gcnW,
                                            (__half2*)encH, (__half2*)WH);
    k_scan<<<1, 1024>>>(cnt, rowptr, rowcur, dis);
    k_scatter<<<(E_EDGES+255)/256, 256>>>(e0, e1, dv, dis, rowcur, colidx, wcsr);

    // 3 GCN layers
    for (int i = 0; i < GCN_NUM; i++){
        k_spmm2<<<(N_POI+7)/8, 256>>>((const uint2*)encH, rowptr, colidx, wcsr, dis,
                                       (uint2*)aggH);
        k_gemm_h<<<(N_POI+127)/128, 256, smem_gemm>>>(
            (const uint2*)aggH, (const uint2*)(WH + i*DIM*DIM), gcnb + i*DIM,
            bA, (__half2*)encH, N_POI, (i == GCN_NUM-1) ? 1 : 0);
    }
    const float* encF = bA;

    // attention
    k_qkv2<<<dim3(NTOK/128, 3), 256, smem_qkv>>>((const float4*)encF, xidx, inw, inb,
                                                 (float4*)qkv);
    k_attn<<<dim3(BATCH, 8), 128, smem_attn>>>(qkv, obuf);
    k_tail<<<BATCH, 128>>>(obuf, ow, ob, encF, pidx, out);
}